// round 1
// baseline (speedup 1.0000x reference)
#include <cuda_runtime.h>
#include <math.h>

#define NV    8192
#define FEAT  1024
#define HID   256
#define CLS   16
#define MAXNB 192

// ---------------- device scratch (no allocations allowed) ----------------
__device__ int   g_col[NV * MAXNB];
__device__ float g_adjv[NV * MAXNB];
__device__ int   g_cnt[NV];
__device__ float g_diag[NV];
__device__ float g_P[NV * HID];     // residual stream
__device__ float g_A[NV * HID];     // Wh
__device__ float g_B[NV * HID];     // layer output
__device__ float g_C16[NV * CLS];   // Wh for layer 2
__device__ float g_O16[NV * CLS];   // layer 2 output (logits)
__device__ float g_norm[NV];
__device__ float g_t2[NV];

__device__ __forceinline__ float softplusf(float x) {
    return x > 20.f ? x : log1pf(expf(x));
}

// ---------------- CSR build from dense adjacency ----------------
__global__ void k_build_csr(const float* __restrict__ adj) {
    int i = blockIdx.x;
    __shared__ int cnt;
    if (threadIdx.x == 0) cnt = 0;
    __syncthreads();
    const float* row = adj + (size_t)i * NV;
    for (int c = threadIdx.x; c < NV; c += blockDim.x) {
        float v = row[c];
        if (v != 0.f) {
            int p = atomicAdd(&cnt, 1);
            if (p < MAXNB) { g_col[i * MAXNB + p] = c; g_adjv[i * MAXNB + p] = v; }
        }
        if (c == i) g_diag[i] = v;
    }
    __syncthreads();
    if (threadIdx.x == 0) g_cnt[i] = cnt < MAXNB ? cnt : MAXNB;
}

// ---------------- tiled fp32 GEMM: C[M,Nc] = A[M,K] @ W[Nc,K]^T + bias ----------------
__global__ __launch_bounds__(256) void k_gemm(
    const float* __restrict__ A, const float* __restrict__ W,
    const float* __restrict__ bias, float* __restrict__ C,
    int M, int Nc, int K, int do_elu)
{
    __shared__ float As[16][64];
    __shared__ float Bs[16][64];
    int bm = blockIdx.x * 64, bn = blockIdx.y * 64;
    int tid = threadIdx.x;
    int lr = tid >> 2, lc = tid & 3;   // loader: row, 4-float group
    int ty = tid >> 4, tx = tid & 15;  // compute: 16x16 thread grid
    float acc[4][4];
#pragma unroll
    for (int i = 0; i < 4; i++)
#pragma unroll
        for (int j = 0; j < 4; j++) acc[i][j] = 0.f;

    for (int k0 = 0; k0 < K; k0 += 16) {
        float4 av = *reinterpret_cast<const float4*>(A + (size_t)(bm + lr) * K + k0 + lc * 4);
        As[lc * 4 + 0][lr] = av.x; As[lc * 4 + 1][lr] = av.y;
        As[lc * 4 + 2][lr] = av.z; As[lc * 4 + 3][lr] = av.w;
        float4 bv = make_float4(0.f, 0.f, 0.f, 0.f);
        if (bn + lr < Nc)
            bv = *reinterpret_cast<const float4*>(W + (size_t)(bn + lr) * K + k0 + lc * 4);
        Bs[lc * 4 + 0][lr] = bv.x; Bs[lc * 4 + 1][lr] = bv.y;
        Bs[lc * 4 + 2][lr] = bv.z; Bs[lc * 4 + 3][lr] = bv.w;
        __syncthreads();
#pragma unroll
        for (int kk = 0; kk < 16; kk++) {
            float4 a4 = *reinterpret_cast<const float4*>(&As[kk][ty * 4]);
            float4 b4 = *reinterpret_cast<const float4*>(&Bs[kk][tx * 4]);
            float a[4] = {a4.x, a4.y, a4.z, a4.w};
            float b[4] = {b4.x, b4.y, b4.z, b4.w};
#pragma unroll
            for (int i = 0; i < 4; i++)
#pragma unroll
                for (int j = 0; j < 4; j++) acc[i][j] += a[i] * b[j];
        }
        __syncthreads();
    }
#pragma unroll
    for (int j = 0; j < 4; j++) {
        int n = bn + tx * 4 + j;
        if (n >= Nc) continue;
        float bb = bias[n];
#pragma unroll
        for (int i = 0; i < 4; i++) {
            float v = acc[i][j] + bb;
            if (do_elu) v = v > 0.f ? v : expm1f(v);
            C[(size_t)(bm + ty * 4 + i) * Nc + n] = v;
        }
    }
}

// ---------------- row L2 norms ----------------
__global__ void k_rownorm(const float* __restrict__ Wh, int D) {
    int row = blockIdx.x * 8 + (threadIdx.x >> 5);
    int lane = threadIdx.x & 31;
    float s = 0.f;
    for (int d = lane; d < D; d += 32) {
        float v = Wh[(size_t)row * D + d];
        s += v * v;
    }
#pragma unroll
    for (int o = 16; o; o >>= 1) s += __shfl_xor_sync(0xffffffffu, s, o);
    if (lane == 0) g_norm[row] = sqrtf(s);
}

// ---------------- sparse attention + aggregation ----------------
// out_i = s * ( c0 * sum_j relu(att_ij) Wh_j + c1 * sum_j min(att_ij,0) Wh_j + c2 * Wh_i )
// att_ij = (Wh_i . Wh_j) / max(|Wh_i||Wh_j|, 1e-9) * adj_ij * softplus(dc0*deg_ij + dc1),
// deg_ij = diag_i/adj_ij - 1, att_ii forced to 0 (skip).
template<int D>
__global__ __launch_bounds__(256) void k_sparse(
    const float* __restrict__ Wh, float* __restrict__ out,
    const float* __restrict__ dc, const float* __restrict__ co,
    const float* __restrict__ sp)
{
    constexpr int R = (D + 31) / 32;
    int i = blockIdx.x;
    int tid = threadIdx.x, w = tid >> 5, lane = tid & 31;
    __shared__ float whi[D];
    __shared__ float accp[8][D];
    __shared__ float accn[8][D];
    for (int d = tid; d < D; d += 256) whi[d] = Wh[(size_t)i * D + d];
    for (int d = lane; d < D; d += 32) { accp[w][d] = 0.f; accn[w][d] = 0.f; }
    __syncthreads();
    float ni = g_norm[i];
    float diag = g_diag[i];
    float dc0 = dc[0], dc1 = dc[1];
    int nn = g_cnt[i];
    for (int t = w; t < nn; t += 8) {
        int j = g_col[i * MAXNB + t];
        if (j == i) continue;
        float a = g_adjv[i * MAXNB + t];
        float wj[R];
        float p = 0.f;
#pragma unroll
        for (int r = 0; r < R; r++) {
            int d = lane + r * 32;
            float v = 0.f;
            if (d < D) { v = Wh[(size_t)j * D + d]; p += whi[d] * v; }
            wj[r] = v;
        }
#pragma unroll
        for (int o = 16; o; o >>= 1) p += __shfl_xor_sync(0xffffffffu, p, o);
        float denom = fmaxf(ni * g_norm[j], 1e-9f);
        float e = p / denom;
        float deg = diag / a - 1.f;
        float sc = softplusf(dc0 * deg + dc1);
        float att = e * a * sc;
        float wp = fmaxf(att, 0.f), wn = fminf(att, 0.f);
#pragma unroll
        for (int r = 0; r < R; r++) {
            int d = lane + r * 32;
            if (d < D) { accp[w][d] += wp * wj[r]; accn[w][d] += wn * wj[r]; }
        }
    }
    __syncthreads();
    // mixing coefficients (softmax of co) and scale (softplus)
    float m = fmaxf(co[0], fmaxf(co[1], co[2]));
    float e0 = expf(co[0] - m), e1 = expf(co[1] - m), e2 = expf(co[2] - m);
    float sden = e0 + e1 + e2;
    float c0 = e0 / sden, c1 = e1 / sden, c2 = e2 / sden;
    float s = softplusf(sp[0]);
    for (int d = tid; d < D; d += 256) {
        float pp = 0.f, nv = 0.f;
#pragma unroll
        for (int ww = 0; ww < 8; ww++) { pp += accp[ww][d]; nv += accn[ww][d]; }
        out[(size_t)i * D + d] = s * (c0 * pp + c1 * nv + c2 * whi[d]);
    }
}

// ---------------- residual: P += coef * elu(B) ----------------
__global__ void k_res(float* __restrict__ P, const float* __restrict__ Bv,
                      float coef, int n) {
    int idx = blockIdx.x * 256 + threadIdx.x;
    if (idx < n) {
        float v = Bv[idx];
        v = v > 0.f ? v : expm1f(v);
        P[idx] += coef * v;
    }
}

// ---------------- head: log_softmax + softmax + top2 ----------------
__global__ void k_head(const float* __restrict__ C, float* __restrict__ logp,
                       float* __restrict__ pred) {
    int g = threadIdx.x >> 4;
    int l = threadIdx.x & 15;
    int row = blockIdx.x * 16 + g;
    float x = C[row * CLS + l];
    float m = x;
#pragma unroll
    for (int o = 8; o; o >>= 1) m = fmaxf(m, __shfl_xor_sync(0xffffffffu, m, o, 16));
    float ex = expf(x - m);
    float se = ex;
#pragma unroll
    for (int o = 8; o; o >>= 1) se += __shfl_xor_sync(0xffffffffu, se, o, 16);
    float lse = logf(se);
    logp[row * CLS + l] = x - m - lse;
    float pr = ex / se;
    pred[row * CLS + l] = pr;
    // top-2 over the 16-lane segment
    int laneid = threadIdx.x & 31;
    int segbase = laneid & 16;
    float m1 = -1.f, m2 = -1.f;
#pragma unroll
    for (int k = 0; k < 16; k++) {
        float v = __shfl_sync(0xffffffffu, pr, segbase + k);
        if (v > m1) { m2 = m1; m1 = v; }
        else if (v > m2) m2 = v;
    }
    if (l == 0) g_t2[row] = m1 + m2;
}

// ---------------- deterministic calib reduction ----------------
__global__ void k_calib(float* __restrict__ out_calib) {
    __shared__ float sh[256];
    float s = 0.f;
    for (int i = threadIdx.x; i < NV; i += 256) s += g_t2[i];
    sh[threadIdx.x] = s;
    __syncthreads();
    for (int o = 128; o; o >>= 1) {
        if (threadIdx.x < o) sh[threadIdx.x] += sh[threadIdx.x + o];
        __syncthreads();
    }
    if (threadIdx.x == 0) out_calib[0] = sh[0] / (float)NV;
}

// ---------------- launcher ----------------
extern "C" void kernel_launch(void* const* d_in, const int* in_sizes, int n_in,
                              void* d_out, int out_size) {
    const float* x    = (const float*)d_in[0];
    const float* adj  = (const float*)d_in[1];
    const float* fcnW = (const float*)d_in[2];
    const float* fcnb = (const float*)d_in[3];
    const float* W0   = (const float*)d_in[4];
    const float* b0   = (const float*)d_in[5];
    const float* dc0  = (const float*)d_in[6];
    const float* c0   = (const float*)d_in[7];
    const float* s0   = (const float*)d_in[8];
    const float* W1   = (const float*)d_in[9];
    const float* b1   = (const float*)d_in[10];
    const float* dc1  = (const float*)d_in[11];
    const float* c1   = (const float*)d_in[12];
    const float* s1   = (const float*)d_in[13];
    const float* W2   = (const float*)d_in[14];
    const float* b2   = (const float*)d_in[15];
    const float* dc2  = (const float*)d_in[16];
    const float* c2   = (const float*)d_in[17];
    const float* s2   = (const float*)d_in[18];

    float* out       = (float*)d_out;
    float* out_logp  = out;                 // [NV*CLS]
    float* out_calib = out + NV * CLS;      // [1]
    float* out_pred  = out + NV * CLS + 1;  // [NV*CLS]

    float *pP, *pA, *pB, *pC16, *pO16;
    cudaGetSymbolAddress((void**)&pP,   g_P);
    cudaGetSymbolAddress((void**)&pA,   g_A);
    cudaGetSymbolAddress((void**)&pB,   g_B);
    cudaGetSymbolAddress((void**)&pC16, g_C16);
    cudaGetSymbolAddress((void**)&pO16, g_O16);

    // CSR from adjacency (also extracts diag for deg)
    k_build_csr<<<NV, 256>>>(adj);

    // prev = elu(x @ fcnW^T + fcnb)
    k_gemm<<<dim3(NV / 64, HID / 64), 256>>>(x, fcnW, fcnb, pP, NV, HID, FEAT, 1);

    // ---- layer 0 (input x) ----
    k_gemm<<<dim3(NV / 64, HID / 64), 256>>>(x, W0, b0, pA, NV, HID, FEAT, 0);
    k_rownorm<<<NV / 8, 256>>>(pA, HID);
    k_sparse<HID><<<NV, 256>>>(pA, pB, dc0, c0, s0);
    k_res<<<NV * HID / 256, 256>>>(pP, pB, 1.0f, NV * HID);

    // ---- layer 1 (input prev) ----
    k_gemm<<<dim3(NV / 64, HID / 64), 256>>>(pP, W1, b1, pA, NV, HID, HID, 0);
    k_rownorm<<<NV / 8, 256>>>(pA, HID);
    k_sparse<HID><<<NV, 256>>>(pA, pB, dc1, c1, s1);
    float decay = (float)log(0.9 / 27.0 + 1.0);  // log(DECAY/(3^EXPO) + 1)
    k_res<<<NV * HID / 256, 256>>>(pP, pB, decay, NV * HID);

    // ---- layer 2 (input prev, D=16) ----
    k_gemm<<<dim3(NV / 64, 1), 256>>>(pP, W2, b2, pC16, NV, CLS, HID, 0);
    k_rownorm<<<NV / 8, 256>>>(pC16, CLS);
    k_sparse<CLS><<<NV, 256>>>(pC16, pO16, dc2, c2, s2);

    // ---- head ----
    k_head<<<NV / 16, 256>>>(pO16, out_logp, out_pred);
    k_calib<<<1, 256>>>(out_calib);
}

// round 2
// speedup vs baseline: 1.2259x; 1.2259x over previous
#include <cuda_runtime.h>
#include <math.h>

#define NV    8192
#define FEAT  1024
#define HID   256
#define CLS   16
#define MAXNB 192

// ---------------- device scratch (no allocations allowed) ----------------
__device__ int   g_col[NV * MAXNB];
__device__ float g_adjv[NV * MAXNB];
__device__ int   g_cnt[NV];
__device__ float g_diag[NV];
__device__ float g_P[NV * HID];     // residual stream
__device__ float g_A[NV * HID];     // Wh
__device__ float g_C16[NV * CLS];   // Wh for layer 2
__device__ float g_O16[NV * CLS];   // layer 2 output (logits)
__device__ float g_norm[NV];
__device__ float g_t2[NV];

__device__ __forceinline__ float softplusf(float x) {
    return x > 20.f ? x : log1pf(expf(x));
}
__device__ __forceinline__ float eluf(float x) {
    return x > 0.f ? x : expm1f(x);
}

// ---------------- CSR build from dense adjacency (float4 scan) ----------------
__global__ void k_build_csr(const float* __restrict__ adj) {
    int i = blockIdx.x;
    __shared__ int cnt;
    if (threadIdx.x == 0) {
        cnt = 0;
        g_diag[i] = adj[(size_t)i * NV + i];
    }
    __syncthreads();
    const float4* row = reinterpret_cast<const float4*>(adj + (size_t)i * NV);
    for (int c4 = threadIdx.x; c4 < NV / 4; c4 += blockDim.x) {
        float4 v = row[c4];
        float vv[4] = {v.x, v.y, v.z, v.w};
#pragma unroll
        for (int q = 0; q < 4; q++) {
            if (vv[q] != 0.f) {
                int p = atomicAdd(&cnt, 1);
                if (p < MAXNB) {
                    g_col[i * MAXNB + p] = c4 * 4 + q;
                    g_adjv[i * MAXNB + p] = vv[q];
                }
            }
        }
    }
    __syncthreads();
    if (threadIdx.x == 0) g_cnt[i] = cnt < MAXNB ? cnt : MAXNB;
}

// ---------------- big tiled fp32 GEMM: C[M,Nc] = A[M,K] @ W[Nc,K]^T + bias ----------------
// 128x128 tile, 8x8 per thread, double-buffered. Requires M%128==0, Nc%128==0, K%16==0.
__global__ __launch_bounds__(256) void k_gemm128(
    const float* __restrict__ A, const float* __restrict__ W,
    const float* __restrict__ bias, float* __restrict__ C,
    int M, int Nc, int K, int do_elu)
{
    __shared__ float As[2][16][128];
    __shared__ float Bs[2][16][128];
    int bm = blockIdx.x * 128, bn = blockIdx.y * 128;
    int tid = threadIdx.x;
    int lr = tid >> 1;            // 0..127
    int lk = (tid & 1) * 8;       // 0 or 8
    int ty = tid >> 4, tx = tid & 15;

    const float* Ap = A + (size_t)(bm + lr) * K + lk;
    const float* Wp = W + (size_t)(bn + lr) * K + lk;

    float acc[8][8];
#pragma unroll
    for (int i = 0; i < 8; i++)
#pragma unroll
        for (int j = 0; j < 8; j++) acc[i][j] = 0.f;

    // prologue: load tile k0=0 into buffer 0
    {
        float4 a0 = *reinterpret_cast<const float4*>(Ap);
        float4 a1 = *reinterpret_cast<const float4*>(Ap + 4);
        float4 b0 = *reinterpret_cast<const float4*>(Wp);
        float4 b1 = *reinterpret_cast<const float4*>(Wp + 4);
        As[0][lk + 0][lr] = a0.x; As[0][lk + 1][lr] = a0.y;
        As[0][lk + 2][lr] = a0.z; As[0][lk + 3][lr] = a0.w;
        As[0][lk + 4][lr] = a1.x; As[0][lk + 5][lr] = a1.y;
        As[0][lk + 6][lr] = a1.z; As[0][lk + 7][lr] = a1.w;
        Bs[0][lk + 0][lr] = b0.x; Bs[0][lk + 1][lr] = b0.y;
        Bs[0][lk + 2][lr] = b0.z; Bs[0][lk + 3][lr] = b0.w;
        Bs[0][lk + 4][lr] = b1.x; Bs[0][lk + 5][lr] = b1.y;
        Bs[0][lk + 6][lr] = b1.z; Bs[0][lk + 7][lr] = b1.w;
    }
    __syncthreads();
    int buf = 0;

    for (int k0 = 16; k0 <= K; k0 += 16) {
        float4 na0, na1, nb0, nb1;
        bool more = (k0 < K);
        if (more) {
            na0 = *reinterpret_cast<const float4*>(Ap + k0);
            na1 = *reinterpret_cast<const float4*>(Ap + k0 + 4);
            nb0 = *reinterpret_cast<const float4*>(Wp + k0);
            nb1 = *reinterpret_cast<const float4*>(Wp + k0 + 4);
        }
#pragma unroll
        for (int kk = 0; kk < 16; kk++) {
            float4 t0 = *reinterpret_cast<const float4*>(&As[buf][kk][ty * 8]);
            float4 t1 = *reinterpret_cast<const float4*>(&As[buf][kk][ty * 8 + 4]);
            float4 u0 = *reinterpret_cast<const float4*>(&Bs[buf][kk][tx * 8]);
            float4 u1 = *reinterpret_cast<const float4*>(&Bs[buf][kk][tx * 8 + 4]);
            float a[8] = {t0.x, t0.y, t0.z, t0.w, t1.x, t1.y, t1.z, t1.w};
            float b[8] = {u0.x, u0.y, u0.z, u0.w, u1.x, u1.y, u1.z, u1.w};
#pragma unroll
            for (int i = 0; i < 8; i++)
#pragma unroll
                for (int j = 0; j < 8; j++) acc[i][j] += a[i] * b[j];
        }
        if (more) {
            int nb = buf ^ 1;
            As[nb][lk + 0][lr] = na0.x; As[nb][lk + 1][lr] = na0.y;
            As[nb][lk + 2][lr] = na0.z; As[nb][lk + 3][lr] = na0.w;
            As[nb][lk + 4][lr] = na1.x; As[nb][lk + 5][lr] = na1.y;
            As[nb][lk + 6][lr] = na1.z; As[nb][lk + 7][lr] = na1.w;
            Bs[nb][lk + 0][lr] = nb0.x; Bs[nb][lk + 1][lr] = nb0.y;
            Bs[nb][lk + 2][lr] = nb0.z; Bs[nb][lk + 3][lr] = nb0.w;
            Bs[nb][lk + 4][lr] = nb1.x; Bs[nb][lk + 5][lr] = nb1.y;
            Bs[nb][lk + 6][lr] = nb1.z; Bs[nb][lk + 7][lr] = nb1.w;
            __syncthreads();
            buf = nb;
        }
    }

    // epilogue: bias + optional ELU, float4 stores
    float bb[8];
#pragma unroll
    for (int j = 0; j < 8; j++) bb[j] = bias[bn + tx * 8 + j];
#pragma unroll
    for (int i = 0; i < 8; i++) {
        float o[8];
#pragma unroll
        for (int j = 0; j < 8; j++) {
            float v = acc[i][j] + bb[j];
            o[j] = do_elu ? eluf(v) : v;
        }
        float* cp = C + (size_t)(bm + ty * 8 + i) * Nc + bn + tx * 8;
        *reinterpret_cast<float4*>(cp)     = make_float4(o[0], o[1], o[2], o[3]);
        *reinterpret_cast<float4*>(cp + 4) = make_float4(o[4], o[5], o[6], o[7]);
    }
}

// ---------------- small GEMM for layer 2 (Nc=16) ----------------
__global__ __launch_bounds__(256) void k_gemm_small(
    const float* __restrict__ A, const float* __restrict__ W,
    const float* __restrict__ bias, float* __restrict__ C,
    int M, int Nc, int K)
{
    __shared__ float Ws[CLS][HID];   // 16x256
    int tid = threadIdx.x;
    for (int idx = tid; idx < Nc * K; idx += 256)
        Ws[idx / K][idx % K] = W[idx];
    __syncthreads();
    // each warp handles one row: lanes cooperate over K, produce 16 outputs
    int row = blockIdx.x * 8 + (tid >> 5);
    int lane = tid & 31;
    const float4* ap = reinterpret_cast<const float4*>(A + (size_t)row * K);
    float4 a0 = ap[lane];        // d = lane*4
    float4 a1 = ap[lane + 32];   // d = 128 + lane*4
    float accv[CLS];
#pragma unroll
    for (int c = 0; c < CLS; c++) {
        float4 w0 = *reinterpret_cast<const float4*>(&Ws[c][lane * 4]);
        float4 w1 = *reinterpret_cast<const float4*>(&Ws[c][lane * 4 + 128]);
        float s = a0.x * w0.x + a0.y * w0.y + a0.z * w0.z + a0.w * w0.w
                + a1.x * w1.x + a1.y * w1.y + a1.z * w1.z + a1.w * w1.w;
#pragma unroll
        for (int o = 16; o; o >>= 1) s += __shfl_xor_sync(0xffffffffu, s, o);
        accv[c] = s + bias[c];
    }
    if (lane < CLS) C[(size_t)row * CLS + lane] = accv[lane];
}

// ---------------- row L2 norms (float4) ----------------
__global__ void k_rownorm(const float* __restrict__ Wh, int D) {
    int row = blockIdx.x * 8 + (threadIdx.x >> 5);
    int lane = threadIdx.x & 31;
    float s = 0.f;
    for (int d = lane * 4; d < D; d += 128) {
        float4 v = *reinterpret_cast<const float4*>(Wh + (size_t)row * D + d);
        s += v.x * v.x + v.y * v.y + v.z * v.z + v.w * v.w;
    }
#pragma unroll
    for (int o = 16; o; o >>= 1) s += __shfl_xor_sync(0xffffffffu, s, o);
    if (lane == 0) g_norm[row] = sqrtf(s);
}

// ---------------- sparse attention + aggregation (+fused residual) ----------------
// out_i = s * ( c0 * sum_j relu(att_ij) Wh_j + c1 * min(att_ij,0) Wh_j + c2 * Wh_i )
// if RES: P_i += coef * elu(out_i)    else: out_i stored raw
template<int D, bool RES>
__global__ __launch_bounds__(256) void k_sparse(
    const float* __restrict__ Wh, float* __restrict__ out,
    const float* __restrict__ dc, const float* __restrict__ co,
    const float* __restrict__ sp, float coef)
{
    int i = blockIdx.x;
    int tid = threadIdx.x, w = tid >> 5, lane = tid & 31;
    __shared__ float whi[D];
    __shared__ float red[8][D];
    for (int d = tid; d < D; d += 256) whi[d] = Wh[(size_t)i * D + d];
    __syncthreads();
    float ni = g_norm[i];
    float diag = g_diag[i];
    float dc0 = dc[0], dc1 = dc[1];
    int nn = g_cnt[i];

    float pp, nv;   // combined pos/neg sums for this thread's output element d=tid

    if constexpr (D == 256) {
        float4 wi0 = *reinterpret_cast<const float4*>(&whi[lane * 4]);
        float4 wi1 = *reinterpret_cast<const float4*>(&whi[lane * 4 + 128]);
        float4 ap0 = make_float4(0, 0, 0, 0), ap1 = ap0, an0 = ap0, an1 = ap0;
        for (int t = w; t < nn; t += 8) {
            int j = g_col[i * MAXNB + t];
            float a = g_adjv[i * MAXNB + t];
            if (j == i) continue;
            const float4* wj = reinterpret_cast<const float4*>(Wh + (size_t)j * D);
            float4 v0 = wj[lane];
            float4 v1 = wj[lane + 32];
            float p = wi0.x * v0.x + wi0.y * v0.y + wi0.z * v0.z + wi0.w * v0.w
                    + wi1.x * v1.x + wi1.y * v1.y + wi1.z * v1.z + wi1.w * v1.w;
#pragma unroll
            for (int o = 16; o; o >>= 1) p += __shfl_xor_sync(0xffffffffu, p, o);
            float denom = fmaxf(ni * g_norm[j], 1e-9f);
            float e = p / denom;
            float deg = diag / a - 1.f;
            float sc = softplusf(dc0 * deg + dc1);
            float att = e * a * sc;
            float wp = fmaxf(att, 0.f), wn = fminf(att, 0.f);
            ap0.x += wp * v0.x; ap0.y += wp * v0.y; ap0.z += wp * v0.z; ap0.w += wp * v0.w;
            ap1.x += wp * v1.x; ap1.y += wp * v1.y; ap1.z += wp * v1.z; ap1.w += wp * v1.w;
            an0.x += wn * v0.x; an0.y += wn * v0.y; an0.z += wn * v0.z; an0.w += wn * v0.w;
            an1.x += wn * v1.x; an1.y += wn * v1.y; an1.z += wn * v1.z; an1.w += wn * v1.w;
        }
        // pos reduce
        *reinterpret_cast<float4*>(&red[w][lane * 4]) = ap0;
        *reinterpret_cast<float4*>(&red[w][lane * 4 + 128]) = ap1;
        __syncthreads();
        pp = 0.f;
#pragma unroll
        for (int ww = 0; ww < 8; ww++) pp += red[ww][tid];
        __syncthreads();
        // neg reduce
        *reinterpret_cast<float4*>(&red[w][lane * 4]) = an0;
        *reinterpret_cast<float4*>(&red[w][lane * 4 + 128]) = an1;
        __syncthreads();
        nv = 0.f;
#pragma unroll
        for (int ww = 0; ww < 8; ww++) nv += red[ww][tid];
    } else {
        // D == 16 scalar path
        float wi = (lane < D) ? whi[lane] : 0.f;
        float ap = 0.f, an = 0.f;
        for (int t = w; t < nn; t += 8) {
            int j = g_col[i * MAXNB + t];
            float a = g_adjv[i * MAXNB + t];
            if (j == i) continue;
            float v = (lane < D) ? Wh[(size_t)j * D + lane] : 0.f;
            float p = wi * v;
#pragma unroll
            for (int o = 16; o; o >>= 1) p += __shfl_xor_sync(0xffffffffu, p, o);
            float denom = fmaxf(ni * g_norm[j], 1e-9f);
            float e = p / denom;
            float deg = diag / a - 1.f;
            float sc = softplusf(dc0 * deg + dc1);
            float att = e * a * sc;
            ap += fmaxf(att, 0.f) * v;
            an += fminf(att, 0.f) * v;
        }
        if (lane < D) red[w][lane] = ap;
        __syncthreads();
        pp = 0.f;
        if (tid < D) {
#pragma unroll
            for (int ww = 0; ww < 8; ww++) pp += red[ww][tid];
        }
        __syncthreads();
        if (lane < D) red[w][lane] = an;
        __syncthreads();
        nv = 0.f;
        if (tid < D) {
#pragma unroll
            for (int ww = 0; ww < 8; ww++) nv += red[ww][tid];
        }
    }

    if (tid < D) {
        float m = fmaxf(co[0], fmaxf(co[1], co[2]));
        float e0 = expf(co[0] - m), e1 = expf(co[1] - m), e2 = expf(co[2] - m);
        float sden = e0 + e1 + e2;
        float c0 = e0 / sden, c1 = e1 / sden, c2 = e2 / sden;
        float s = softplusf(sp[0]);
        float val = s * (c0 * pp + c1 * nv + c2 * whi[tid]);
        if (RES)
            out[(size_t)i * D + tid] += coef * eluf(val);
        else
            out[(size_t)i * D + tid] = val;
    }
}

// ---------------- head: log_softmax + softmax + top2 ----------------
__global__ void k_head(const float* __restrict__ C, float* __restrict__ logp,
                       float* __restrict__ pred) {
    int g = threadIdx.x >> 4;
    int l = threadIdx.x & 15;
    int row = blockIdx.x * 16 + g;
    float x = C[row * CLS + l];
    float m = x;
#pragma unroll
    for (int o = 8; o; o >>= 1) m = fmaxf(m, __shfl_xor_sync(0xffffffffu, m, o, 16));
    float ex = expf(x - m);
    float se = ex;
#pragma unroll
    for (int o = 8; o; o >>= 1) se += __shfl_xor_sync(0xffffffffu, se, o, 16);
    float lse = logf(se);
    logp[row * CLS + l] = x - m - lse;
    float pr = ex / se;
    pred[row * CLS + l] = pr;
    int laneid = threadIdx.x & 31;
    int segbase = laneid & 16;
    float m1 = -1.f, m2 = -1.f;
#pragma unroll
    for (int k = 0; k < 16; k++) {
        float v = __shfl_sync(0xffffffffu, pr, segbase + k);
        if (v > m1) { m2 = m1; m1 = v; }
        else if (v > m2) m2 = v;
    }
    if (l == 0) g_t2[row] = m1 + m2;
}

// ---------------- deterministic calib reduction ----------------
__global__ void k_calib(float* __restrict__ out_calib) {
    __shared__ float sh[256];
    float s = 0.f;
    for (int i = threadIdx.x; i < NV; i += 256) s += g_t2[i];
    sh[threadIdx.x] = s;
    __syncthreads();
    for (int o = 128; o; o >>= 1) {
        if (threadIdx.x < o) sh[threadIdx.x] += sh[threadIdx.x + o];
        __syncthreads();
    }
    if (threadIdx.x == 0) out_calib[0] = sh[0] / (float)NV;
}

// ---------------- launcher ----------------
extern "C" void kernel_launch(void* const* d_in, const int* in_sizes, int n_in,
                              void* d_out, int out_size) {
    const float* x    = (const float*)d_in[0];
    const float* adj  = (const float*)d_in[1];
    const float* fcnW = (const float*)d_in[2];
    const float* fcnb = (const float*)d_in[3];
    const float* W0   = (const float*)d_in[4];
    const float* b0   = (const float*)d_in[5];
    const float* dc0  = (const float*)d_in[6];
    const float* c0   = (const float*)d_in[7];
    const float* s0   = (const float*)d_in[8];
    const float* W1   = (const float*)d_in[9];
    const float* b1   = (const float*)d_in[10];
    const float* dc1  = (const float*)d_in[11];
    const float* c1   = (const float*)d_in[12];
    const float* s1   = (const float*)d_in[13];
    const float* W2   = (const float*)d_in[14];
    const float* b2   = (const float*)d_in[15];
    const float* dc2  = (const float*)d_in[16];
    const float* c2   = (const float*)d_in[17];
    const float* s2   = (const float*)d_in[18];

    float* out       = (float*)d_out;
    float* out_logp  = out;                 // [NV*CLS]
    float* out_calib = out + NV * CLS;      // [1]
    float* out_pred  = out + NV * CLS + 1;  // [NV*CLS]

    float *pP, *pA, *pC16, *pO16;
    cudaGetSymbolAddress((void**)&pP,   g_P);
    cudaGetSymbolAddress((void**)&pA,   g_A);
    cudaGetSymbolAddress((void**)&pC16, g_C16);
    cudaGetSymbolAddress((void**)&pO16, g_O16);

    // CSR from adjacency (also extracts diag)
    k_build_csr<<<NV, 256>>>(adj);

    // prev = elu(x @ fcnW^T + fcnb)
    k_gemm128<<<dim3(NV / 128, HID / 128), 256>>>(x, fcnW, fcnb, pP, NV, HID, FEAT, 1);

    // ---- layer 0 (input x) ----
    k_gemm128<<<dim3(NV / 128, HID / 128), 256>>>(x, W0, b0, pA, NV, HID, FEAT, 0);
    k_rownorm<<<NV / 8, 256>>>(pA, HID);
    k_sparse<HID, true><<<NV, 256>>>(pA, pP, dc0, c0, s0, 1.0f);

    // ---- layer 1 (input prev) ----
    k_gemm128<<<dim3(NV / 128, HID / 128), 256>>>(pP, W1, b1, pA, NV, HID, HID, 0);
    k_rownorm<<<NV / 8, 256>>>(pA, HID);
    float decay = (float)log(0.9 / 27.0 + 1.0);  // log(DECAY/(3^EXPO) + 1)
    k_sparse<HID, true><<<NV, 256>>>(pA, pP, dc1, c1, s1, decay);

    // ---- layer 2 (input prev, D=16) ----
    k_gemm_small<<<NV / 8, 256>>>(pP, W2, b2, pC16, NV, CLS, HID);
    k_rownorm<<<NV / 8, 256>>>(pC16, CLS);
    k_sparse<CLS, false><<<NV, 256>>>(pC16, pO16, dc2, c2, s2, 0.0f);

    // ---- head ----
    k_head<<<NV / 16, 256>>>(pO16, out_logp, out_pred);
    k_calib<<<1, 256>>>(out_calib);
}

// round 4
// speedup vs baseline: 1.6188x; 1.3205x over previous
#include <cuda_runtime.h>
#include <cuda_bf16.h>
#include <math.h>
#include <stdint.h>

#define NV    8192
#define FEAT  1024
#define HID   256
#define CLS   16
#define MAXNB 192

// ---------------- device scratch (no allocations allowed) ----------------
__device__ int   g_col[NV * MAXNB];
__device__ float g_adjv[NV * MAXNB];
__device__ int   g_cnt[NV];
__device__ float g_diag[NV];
__device__ float g_P[NV * HID];     // residual stream
__device__ float g_A[NV * HID];     // Wh
__device__ float g_C16[NV * CLS];
__device__ float g_O16[NV * CLS];
__device__ float g_norm[NV];
__device__ float g_t2[NV];
// bf16 hi/lo splits for tensor-core GEMM
__device__ __nv_bfloat16 g_xhi[NV * FEAT];
__device__ __nv_bfloat16 g_xlo[NV * FEAT];
__device__ __nv_bfloat16 g_phi[NV * HID];
__device__ __nv_bfloat16 g_plo[NV * HID];
__device__ __nv_bfloat16 g_whi[HID * FEAT];
__device__ __nv_bfloat16 g_wlo[HID * FEAT];

__device__ __forceinline__ float softplusf(float x) {
    return x > 20.f ? x : log1pf(expf(x));
}
__device__ __forceinline__ float eluf(float x) {
    return x > 0.f ? x : expm1f(x);
}
__device__ __forceinline__ uint32_t smem_to_u32(const void* smem_ptr) {
    uint32_t addr;
    asm("{ .reg .u64 tmp; cvta.to.shared.u64 tmp, %1; cvt.u32.u64 %0, tmp; }"
        : "=r"(addr) : "l"(smem_ptr));
    return addr;
}
__device__ __forceinline__ void cp16(uint32_t dst, const void* src) {
    asm volatile("cp.async.cg.shared.global [%0], [%1], 16;"
                 :: "r"(dst), "l"(src) : "memory");
}
#define CP_COMMIT() asm volatile("cp.async.commit_group;" ::: "memory")
#define CP_WAIT0()  asm volatile("cp.async.wait_group 0;" ::: "memory")
#define CP_WAIT1()  asm volatile("cp.async.wait_group 1;" ::: "memory")

__device__ __forceinline__ void mma16816(float* d, const uint32_t* a, const uint32_t* b) {
    asm volatile(
        "mma.sync.aligned.m16n8k16.row.col.f32.bf16.bf16.f32 "
        "{%0,%1,%2,%3}, {%4,%5,%6,%7}, {%8,%9}, {%0,%1,%2,%3};"
        : "+f"(d[0]), "+f"(d[1]), "+f"(d[2]), "+f"(d[3])
        : "r"(a[0]), "r"(a[1]), "r"(a[2]), "r"(a[3]), "r"(b[0]), "r"(b[1]));
}

// ---------------- CSR build from dense adjacency ----------------
__global__ void k_build_csr(const float* __restrict__ adj) {
    int i = blockIdx.x;
    __shared__ int cnt;
    if (threadIdx.x == 0) {
        cnt = 0;
        g_diag[i] = adj[(size_t)i * NV + i];
    }
    __syncthreads();
    const float4* row = reinterpret_cast<const float4*>(adj + (size_t)i * NV);
    for (int c4 = threadIdx.x; c4 < NV / 4; c4 += blockDim.x) {
        float4 v = row[c4];
        float vv[4] = {v.x, v.y, v.z, v.w};
#pragma unroll
        for (int q = 0; q < 4; q++) {
            if (vv[q] != 0.f) {
                int p = atomicAdd(&cnt, 1);
                if (p < MAXNB) {
                    g_col[i * MAXNB + p] = c4 * 4 + q;
                    g_adjv[i * MAXNB + p] = vv[q];
                }
            }
        }
    }
    __syncthreads();
    if (threadIdx.x == 0) g_cnt[i] = cnt < MAXNB ? cnt : MAXNB;
}

// ---------------- fp32 -> bf16 hi/lo split ----------------
__global__ void k_split(const float* __restrict__ X,
                        __nv_bfloat16* __restrict__ hi,
                        __nv_bfloat16* __restrict__ lo, int n4) {
    int idx = blockIdx.x * 256 + threadIdx.x;
    if (idx >= n4) return;
    float4 v = reinterpret_cast<const float4*>(X)[idx];
    float xs[4] = {v.x, v.y, v.z, v.w};
    __nv_bfloat16 h[4], l[4];
#pragma unroll
    for (int q = 0; q < 4; q++) {
        h[q] = __float2bfloat16(xs[q]);
        l[q] = __float2bfloat16(xs[q] - __bfloat162float(h[q]));
    }
    __nv_bfloat162* hp = reinterpret_cast<__nv_bfloat162*>(hi) + idx * 2;
    __nv_bfloat162* lp = reinterpret_cast<__nv_bfloat162*>(lo) + idx * 2;
    hp[0] = __nv_bfloat162(h[0], h[1]); hp[1] = __nv_bfloat162(h[2], h[3]);
    lp[0] = __nv_bfloat162(l[0], l[1]); lp[1] = __nv_bfloat162(l[2], l[3]);
}

// ---------------- mma.sync bf16 GEMM: C[M,256] = A[M,K] @ W[256,K]^T + bias ----------------
// 3xBF16: C = Ah*Bh + Ah*Bl + Al*Bh. CTA tile 128x128 (grid.y=2). 8 warps, each 64x32.
// K chunks of 32, double-buffered via cp.async. smem rows padded to 80B (conflict-free).
#define G_ROWB   80         // bytes per smem row (32 bf16 padded to 40)
#define G_TILE   (128 * G_ROWB)   // 10240
#define G_STAGE  (4 * G_TILE)     // Ah|Al|Bh|Bl = 40960
#define G_SMEM   (2 * G_STAGE)    // 81920

__device__ __forceinline__ void g_issue_chunk(
    uint32_t sst,
    const __nv_bfloat16* __restrict__ Ah, const __nv_bfloat16* __restrict__ Al,
    const __nv_bfloat16* __restrict__ Bh, const __nv_bfloat16* __restrict__ Bl,
    int bm, int bn, int K, int k0, int tid)
{
#pragma unroll
    for (int t = 0; t < 2; t++) {
        int idx = tid + t * 256;
        int row = idx >> 2, q = idx & 3;
        uint32_t so = row * G_ROWB + q * 16;
        cp16(sst + so,              Ah + (size_t)(bm + row) * K + k0 + q * 8);
        cp16(sst + G_TILE + so,     Al + (size_t)(bm + row) * K + k0 + q * 8);
        cp16(sst + 2 * G_TILE + so, Bh + (size_t)(bn + row) * K + k0 + q * 8);
        cp16(sst + 3 * G_TILE + so, Bl + (size_t)(bn + row) * K + k0 + q * 8);
    }
    CP_COMMIT();
}

__global__ __launch_bounds__(256, 1)
void k_mma_gemm(const __nv_bfloat16* __restrict__ Ah, const __nv_bfloat16* __restrict__ Al,
                const __nv_bfloat16* __restrict__ Bh, const __nv_bfloat16* __restrict__ Bl,
                const float* __restrict__ bias, float* __restrict__ C,
                int K, int do_elu)
{
    extern __shared__ char smem[];
    uint32_t sb = smem_to_u32(smem);
    int tid = threadIdx.x;
    int wid = tid >> 5, lane = tid & 31;
    int wm = wid >> 2, wn = wid & 3;        // warp tile: rows wm*64, cols wn*32
    int gid = lane >> 2, tk = (lane & 3) * 2;
    int bm = blockIdx.x * 128, bn = blockIdx.y * 128;

    float d[4][4][4];
#pragma unroll
    for (int ma = 0; ma < 4; ma++)
#pragma unroll
        for (int na = 0; na < 4; na++)
#pragma unroll
            for (int q = 0; q < 4; q++) d[ma][na][q] = 0.f;

    int NC = K / 32;
    g_issue_chunk(sb, Ah, Al, Bh, Bl, bm, bn, K, 0, tid);

    for (int c = 0; c < NC; c++) {
        bool more = (c + 1 < NC);
        if (more) {
            g_issue_chunk(sb + ((c + 1) & 1) * G_STAGE, Ah, Al, Bh, Bl,
                          bm, bn, K, (c + 1) * 32, tid);
            CP_WAIT1();
        } else {
            CP_WAIT0();
        }
        __syncthreads();

        const char* st = smem + (c & 1) * G_STAGE;
        const char* sAh = st;
        const char* sAl = st + G_TILE;
        const char* sBh = st + 2 * G_TILE;
        const char* sBl = st + 3 * G_TILE;

#pragma unroll
        for (int kk2 = 0; kk2 < 2; kk2++) {
            int kk = kk2 * 16;
            uint32_t ah[4][4], al[4][4], bh[4][2], bl[4][2];
#pragma unroll
            for (int ma = 0; ma < 4; ma++) {
                int rb = wm * 64 + ma * 16;
                int o00 = (rb + gid) * G_ROWB + (kk + tk) * 2;
                int o10 = (rb + gid + 8) * G_ROWB + (kk + tk) * 2;
                ah[ma][0] = *(const uint32_t*)(sAh + o00);
                ah[ma][1] = *(const uint32_t*)(sAh + o10);
                ah[ma][2] = *(const uint32_t*)(sAh + o00 + 16);
                ah[ma][3] = *(const uint32_t*)(sAh + o10 + 16);
                al[ma][0] = *(const uint32_t*)(sAl + o00);
                al[ma][1] = *(const uint32_t*)(sAl + o10);
                al[ma][2] = *(const uint32_t*)(sAl + o00 + 16);
                al[ma][3] = *(const uint32_t*)(sAl + o10 + 16);
            }
#pragma unroll
            for (int na = 0; na < 4; na++) {
                int nb = wn * 32 + na * 8 + gid;
                int o = nb * G_ROWB + (kk + tk) * 2;
                bh[na][0] = *(const uint32_t*)(sBh + o);
                bh[na][1] = *(const uint32_t*)(sBh + o + 16);
                bl[na][0] = *(const uint32_t*)(sBl + o);
                bl[na][1] = *(const uint32_t*)(sBl + o + 16);
            }
#pragma unroll
            for (int ma = 0; ma < 4; ma++)
#pragma unroll
                for (int na = 0; na < 4; na++) {
                    mma16816(d[ma][na], ah[ma], bh[na]);
                    mma16816(d[ma][na], ah[ma], bl[na]);
                    mma16816(d[ma][na], al[ma], bh[na]);
                }
        }
        __syncthreads();
    }

    // epilogue: bias + optional ELU
#pragma unroll
    for (int ma = 0; ma < 4; ma++) {
        int r0 = bm + wm * 64 + ma * 16 + gid;
#pragma unroll
        for (int na = 0; na < 4; na++) {
            int col = bn + wn * 32 + na * 8 + tk;
            float b0 = bias[col], b1 = bias[col + 1];
            float v0 = d[ma][na][0] + b0, v1 = d[ma][na][1] + b1;
            float v2 = d[ma][na][2] + b0, v3 = d[ma][na][3] + b1;
            if (do_elu) { v0 = eluf(v0); v1 = eluf(v1); v2 = eluf(v2); v3 = eluf(v3); }
            *reinterpret_cast<float2*>(C + (size_t)r0 * 256 + col)       = make_float2(v0, v1);
            *reinterpret_cast<float2*>(C + (size_t)(r0 + 8) * 256 + col) = make_float2(v2, v3);
        }
    }
}

// ---------------- small GEMM for layer 2 (Nc=16) ----------------
__global__ __launch_bounds__(256) void k_gemm_small(
    const float* __restrict__ A, const float* __restrict__ W,
    const float* __restrict__ bias, float* __restrict__ C,
    int M, int Nc, int K)
{
    __shared__ float Ws[CLS][HID];
    int tid = threadIdx.x;
    for (int idx = tid; idx < Nc * K; idx += 256)
        Ws[idx / K][idx % K] = W[idx];
    __syncthreads();
    int row = blockIdx.x * 8 + (tid >> 5);
    int lane = tid & 31;
    const float4* ap = reinterpret_cast<const float4*>(A + (size_t)row * K);
    float4 a0 = ap[lane];
    float4 a1 = ap[lane + 32];
    float accv[CLS];
#pragma unroll
    for (int c = 0; c < CLS; c++) {
        float4 w0 = *reinterpret_cast<const float4*>(&Ws[c][lane * 4]);
        float4 w1 = *reinterpret_cast<const float4*>(&Ws[c][lane * 4 + 128]);
        float s = a0.x * w0.x + a0.y * w0.y + a0.z * w0.z + a0.w * w0.w
                + a1.x * w1.x + a1.y * w1.y + a1.z * w1.z + a1.w * w1.w;
#pragma unroll
        for (int o = 16; o; o >>= 1) s += __shfl_xor_sync(0xffffffffu, s, o);
        accv[c] = s + bias[c];
    }
    if (lane < CLS) C[(size_t)row * CLS + lane] = accv[lane];
}

// ---------------- row L2 norms (float4) ----------------
__global__ void k_rownorm(const float* __restrict__ Wh, int D) {
    int row = blockIdx.x * 8 + (threadIdx.x >> 5);
    int lane = threadIdx.x & 31;
    float s = 0.f;
    for (int d = lane * 4; d < D; d += 128) {
        float4 v = *reinterpret_cast<const float4*>(Wh + (size_t)row * D + d);
        s += v.x * v.x + v.y * v.y + v.z * v.z + v.w * v.w;
    }
#pragma unroll
    for (int o = 16; o; o >>= 1) s += __shfl_xor_sync(0xffffffffu, s, o);
    if (lane == 0) g_norm[row] = sqrtf(s);
}

// ---------------- sparse attention + aggregation (+fused residual) ----------------
template<int D, bool RES>
__global__ __launch_bounds__(256) void k_sparse(
    const float* __restrict__ Wh, float* __restrict__ out,
    const float* __restrict__ dc, const float* __restrict__ co,
    const float* __restrict__ sp, float coef)
{
    int i = blockIdx.x;
    int tid = threadIdx.x, w = tid >> 5, lane = tid & 31;
    __shared__ float whi[D];
    __shared__ float red[8][D];
    for (int d = tid; d < D; d += 256) whi[d] = Wh[(size_t)i * D + d];
    __syncthreads();
    float ni = g_norm[i];
    float diag = g_diag[i];
    float dc0 = dc[0], dc1 = dc[1];
    int nn = g_cnt[i];

    float pp, nv;

    if constexpr (D == 256) {
        float4 wi0 = *reinterpret_cast<const float4*>(&whi[lane * 4]);
        float4 wi1 = *reinterpret_cast<const float4*>(&whi[lane * 4 + 128]);
        float4 ap0 = make_float4(0, 0, 0, 0), ap1 = ap0, an0 = ap0, an1 = ap0;
        for (int t = w; t < nn; t += 8) {
            int j = g_col[i * MAXNB + t];
            float a = g_adjv[i * MAXNB + t];
            if (j == i) continue;
            const float4* wj = reinterpret_cast<const float4*>(Wh + (size_t)j * D);
            float4 v0 = wj[lane];
            float4 v1 = wj[lane + 32];
            float p = wi0.x * v0.x + wi0.y * v0.y + wi0.z * v0.z + wi0.w * v0.w
                    + wi1.x * v1.x + wi1.y * v1.y + wi1.z * v1.z + wi1.w * v1.w;
#pragma unroll
            for (int o = 16; o; o >>= 1) p += __shfl_xor_sync(0xffffffffu, p, o);
            float denom = fmaxf(ni * g_norm[j], 1e-9f);
            float e = p / denom;
            float deg = diag / a - 1.f;
            float sc = softplusf(dc0 * deg + dc1);
            float att = e * a * sc;
            float wp = fmaxf(att, 0.f), wn = fminf(att, 0.f);
            ap0.x += wp * v0.x; ap0.y += wp * v0.y; ap0.z += wp * v0.z; ap0.w += wp * v0.w;
            ap1.x += wp * v1.x; ap1.y += wp * v1.y; ap1.z += wp * v1.z; ap1.w += wp * v1.w;
            an0.x += wn * v0.x; an0.y += wn * v0.y; an0.z += wn * v0.z; an0.w += wn * v0.w;
            an1.x += wn * v1.x; an1.y += wn * v1.y; an1.z += wn * v1.z; an1.w += wn * v1.w;
        }
        *reinterpret_cast<float4*>(&red[w][lane * 4]) = ap0;
        *reinterpret_cast<float4*>(&red[w][lane * 4 + 128]) = ap1;
        __syncthreads();
        pp = 0.f;
#pragma unroll
        for (int ww = 0; ww < 8; ww++) pp += red[ww][tid];
        __syncthreads();
        *reinterpret_cast<float4*>(&red[w][lane * 4]) = an0;
        *reinterpret_cast<float4*>(&red[w][lane * 4 + 128]) = an1;
        __syncthreads();
        nv = 0.f;
#pragma unroll
        for (int ww = 0; ww < 8; ww++) nv += red[ww][tid];
    } else {
        float wi = (lane < D) ? whi[lane] : 0.f;
        float ap = 0.f, an = 0.f;
        for (int t = w; t < nn; t += 8) {
            int j = g_col[i * MAXNB + t];
            float a = g_adjv[i * MAXNB + t];
            if (j == i) continue;
            float v = (lane < D) ? Wh[(size_t)j * D + lane] : 0.f;
            float p = wi * v;
#pragma unroll
            for (int o = 16; o; o >>= 1) p += __shfl_xor_sync(0xffffffffu, p, o);
            float denom = fmaxf(ni * g_norm[j], 1e-9f);
            float e = p / denom;
            float deg = diag / a - 1.f;
            float sc = softplusf(dc0 * deg + dc1);
            float att = e * a * sc;
            ap += fmaxf(att, 0.f) * v;
            an += fminf(att, 0.f) * v;
        }
        if (lane < D) red[w][lane] = ap;
        __syncthreads();
        pp = 0.f;
        if (tid < D) {
#pragma unroll
            for (int ww = 0; ww < 8; ww++) pp += red[ww][tid];
        }
        __syncthreads();
        if (lane < D) red[w][lane] = an;
        __syncthreads();
        nv = 0.f;
        if (tid < D) {
#pragma unroll
            for (int ww = 0; ww < 8; ww++) nv += red[ww][tid];
        }
    }

    if (tid < D) {
        float m = fmaxf(co[0], fmaxf(co[1], co[2]));
        float e0 = expf(co[0] - m), e1 = expf(co[1] - m), e2 = expf(co[2] - m);
        float sden = e0 + e1 + e2;
        float c0 = e0 / sden, c1 = e1 / sden, c2 = e2 / sden;
        float s = softplusf(sp[0]);
        float val = s * (c0 * pp + c1 * nv + c2 * whi[tid]);
        if (RES)
            out[(size_t)i * D + tid] += coef * eluf(val);
        else
            out[(size_t)i * D + tid] = val;
    }
}

// ---------------- head: log_softmax + softmax + top2 ----------------
__global__ void k_head(const float* __restrict__ C, float* __restrict__ logp,
                       float* __restrict__ pred) {
    int g = threadIdx.x >> 4;
    int l = threadIdx.x & 15;
    int row = blockIdx.x * 16 + g;
    float x = C[row * CLS + l];
    float m = x;
#pragma unroll
    for (int o = 8; o; o >>= 1) m = fmaxf(m, __shfl_xor_sync(0xffffffffu, m, o, 16));
    float ex = expf(x - m);
    float se = ex;
#pragma unroll
    for (int o = 8; o; o >>= 1) se += __shfl_xor_sync(0xffffffffu, se, o, 16);
    float lse = logf(se);
    logp[row * CLS + l] = x - m - lse;
    float pr = ex / se;
    pred[row * CLS + l] = pr;
    int laneid = threadIdx.x & 31;
    int segbase = laneid & 16;
    float m1 = -1.f, m2 = -1.f;
#pragma unroll
    for (int k = 0; k < 16; k++) {
        float v = __shfl_sync(0xffffffffu, pr, segbase + k);
        if (v > m1) { m2 = m1; m1 = v; }
        else if (v > m2) m2 = v;
    }
    if (l == 0) g_t2[row] = m1 + m2;
}

// ---------------- deterministic calib reduction ----------------
__global__ void k_calib(float* __restrict__ out_calib) {
    __shared__ float sh[256];
    float s = 0.f;
    for (int i = threadIdx.x; i < NV; i += 256) s += g_t2[i];
    sh[threadIdx.x] = s;
    __syncthreads();
    for (int o = 128; o; o >>= 1) {
        if (threadIdx.x < o) sh[threadIdx.x] += sh[threadIdx.x + o];
        __syncthreads();
    }
    if (threadIdx.x == 0) out_calib[0] = sh[0] / (float)NV;
}

// ---------------- launcher ----------------
extern "C" void kernel_launch(void* const* d_in, const int* in_sizes, int n_in,
                              void* d_out, int out_size) {
    const float* x    = (const float*)d_in[0];
    const float* adj  = (const float*)d_in[1];
    const float* fcnW = (const float*)d_in[2];
    const float* fcnb = (const float*)d_in[3];
    const float* W0   = (const float*)d_in[4];
    const float* b0   = (const float*)d_in[5];
    const float* dc0  = (const float*)d_in[6];
    const float* c0   = (const float*)d_in[7];
    const float* s0   = (const float*)d_in[8];
    const float* W1   = (const float*)d_in[9];
    const float* b1   = (const float*)d_in[10];
    const float* dc1  = (const float*)d_in[11];
    const float* c1   = (const float*)d_in[12];
    const float* s1   = (const float*)d_in[13];
    const float* W2   = (const float*)d_in[14];
    const float* b2   = (const float*)d_in[15];
    const float* dc2  = (const float*)d_in[16];
    const float* c2   = (const float*)d_in[17];
    const float* s2   = (const float*)d_in[18];

    float* out       = (float*)d_out;
    float* out_logp  = out;
    float* out_calib = out + NV * CLS;
    float* out_pred  = out + NV * CLS + 1;

    float *pP, *pA, *pC16, *pO16;
    cudaGetSymbolAddress((void**)&pP,   g_P);
    cudaGetSymbolAddress((void**)&pA,   g_A);
    cudaGetSymbolAddress((void**)&pC16, g_C16);
    cudaGetSymbolAddress((void**)&pO16, g_O16);
    __nv_bfloat16 *pxh, *pxl, *pph, *ppl, *pwh, *pwl;
    cudaGetSymbolAddress((void**)&pxh, g_xhi);
    cudaGetSymbolAddress((void**)&pxl, g_xlo);
    cudaGetSymbolAddress((void**)&pph, g_phi);
    cudaGetSymbolAddress((void**)&ppl, g_plo);
    cudaGetSymbolAddress((void**)&pwh, g_whi);
    cudaGetSymbolAddress((void**)&pwl, g_wlo);

    cudaFuncSetAttribute(k_mma_gemm, cudaFuncAttributeMaxDynamicSharedMemorySize, G_SMEM);

    // CSR from adjacency (also extracts diag)
    k_build_csr<<<NV, 256>>>(adj);

    // split x once
    k_split<<<(NV * FEAT / 4 + 255) / 256, 256>>>(x, pxh, pxl, NV * FEAT / 4);

    // prev = elu(x @ fcnW^T + fcnb)
    k_split<<<(HID * FEAT / 4 + 255) / 256, 256>>>(fcnW, pwh, pwl, HID * FEAT / 4);
    k_mma_gemm<<<dim3(NV / 128, 2), 256, G_SMEM>>>(pxh, pxl, pwh, pwl, fcnb, pP, FEAT, 1);

    // ---- layer 0 (input x) ----
    k_split<<<(HID * FEAT / 4 + 255) / 256, 256>>>(W0, pwh, pwl, HID * FEAT / 4);
    k_mma_gemm<<<dim3(NV / 128, 2), 256, G_SMEM>>>(pxh, pxl, pwh, pwl, b0, pA, FEAT, 0);
    k_rownorm<<<NV / 8, 256>>>(pA, HID);
    k_sparse<HID, true><<<NV, 256>>>(pA, pP, dc0, c0, s0, 1.0f);

    // ---- layer 1 (input prev) ----
    k_split<<<(NV * HID / 4 + 255) / 256, 256>>>(pP, pph, ppl, NV * HID / 4);
    k_split<<<(HID * HID / 4 + 255) / 256, 256>>>(W1, pwh, pwl, HID * HID / 4);
    k_mma_gemm<<<dim3(NV / 128, 2), 256, G_SMEM>>>(pph, ppl, pwh, pwl, b1, pA, HID, 0);
    k_rownorm<<<NV / 8, 256>>>(pA, HID);
    float decay = (float)log(0.9 / 27.0 + 1.0);
    k_sparse<HID, true><<<NV, 256>>>(pA, pP, dc1, c1, s1, decay);

    // ---- layer 2 (input prev, D=16) ----
    k_gemm_small<<<NV / 8, 256>>>(pP, W2, b2, pC16, NV, CLS, HID);
    k_rownorm<<<NV / 8, 256>>>(pC16, CLS);
    k_sparse<CLS, false><<<NV, 256>>>(pC16, pO16, dc2, c2, s2, 0.0f);

    // ---- head ----
    k_head<<<NV / 16, 256>>>(pO16, out_logp, out_pred);
    k_calib<<<1, 256>>>(out_calib);
}

// round 5
// speedup vs baseline: 1.6274x; 1.0053x over previous
#include <cuda_runtime.h>
#include <cuda_bf16.h>
#include <math.h>
#include <stdint.h>

#define NV    8192
#define FEAT  1024
#define HID   256
#define CLS   16
#define MAXNB 192

// ---------------- device scratch (no allocations allowed) ----------------
__device__ int   g_col[NV * MAXNB];
__device__ float g_adjv[NV * MAXNB];
__device__ int   g_cnt[NV];
__device__ float g_diag[NV];
__device__ float g_P[NV * HID];     // residual stream
__device__ float g_A[NV * HID];     // Wh
__device__ float g_C16[NV * CLS];
__device__ float g_O16[NV * CLS];
__device__ float g_norm[NV];
__device__ float g_t2[NV];
// bf16 hi/lo splits for tensor-core GEMM
__device__ __nv_bfloat16 g_xhi[NV * FEAT];
__device__ __nv_bfloat16 g_xlo[NV * FEAT];
__device__ __nv_bfloat16 g_phi[NV * HID];
__device__ __nv_bfloat16 g_plo[NV * HID];
__device__ __nv_bfloat16 g_whi[2 * HID * FEAT];
__device__ __nv_bfloat16 g_wlo[2 * HID * FEAT];

__device__ __forceinline__ float softplusf(float x) {
    return x > 20.f ? x : log1pf(expf(x));
}
__device__ __forceinline__ float eluf(float x) {
    return x > 0.f ? x : expm1f(x);
}
__device__ __forceinline__ uint32_t smem_to_u32(const void* smem_ptr) {
    uint32_t addr;
    asm("{ .reg .u64 tmp; cvta.to.shared.u64 tmp, %1; cvt.u32.u64 %0, tmp; }"
        : "=r"(addr) : "l"(smem_ptr));
    return addr;
}
__device__ __forceinline__ void cp16(uint32_t dst, const void* src) {
    asm volatile("cp.async.cg.shared.global [%0], [%1], 16;"
                 :: "r"(dst), "l"(src) : "memory");
}
#define CP_COMMIT() asm volatile("cp.async.commit_group;" ::: "memory")
#define CP_WAIT0()  asm volatile("cp.async.wait_group 0;" ::: "memory")
#define CP_WAIT1()  asm volatile("cp.async.wait_group 1;" ::: "memory")

__device__ __forceinline__ void mma16816(float* d, const uint32_t* a, const uint32_t* b) {
    asm volatile(
        "mma.sync.aligned.m16n8k16.row.col.f32.bf16.bf16.f32 "
        "{%0,%1,%2,%3}, {%4,%5,%6,%7}, {%8,%9}, {%0,%1,%2,%3};"
        : "+f"(d[0]), "+f"(d[1]), "+f"(d[2]), "+f"(d[3])
        : "r"(a[0]), "r"(a[1]), "r"(a[2]), "r"(a[3]), "r"(b[0]), "r"(b[1]));
}
__device__ __forceinline__ void ldsm_x4(uint32_t* r, uint32_t addr) {
    asm volatile("ldmatrix.sync.aligned.m8n8.x4.shared.b16 {%0,%1,%2,%3}, [%4];"
        : "=r"(r[0]), "=r"(r[1]), "=r"(r[2]), "=r"(r[3]) : "r"(addr));
}

// ---------------- CSR build from dense adjacency ----------------
__global__ void k_build_csr(const float* __restrict__ adj) {
    int i = blockIdx.x;
    __shared__ int cnt;
    if (threadIdx.x == 0) {
        cnt = 0;
        g_diag[i] = adj[(size_t)i * NV + i];
    }
    __syncthreads();
    const float4* row = reinterpret_cast<const float4*>(adj + (size_t)i * NV);
    for (int c4 = threadIdx.x; c4 < NV / 4; c4 += blockDim.x) {
        float4 v = __ldcs(&row[c4]);
        float vv[4] = {v.x, v.y, v.z, v.w};
#pragma unroll
        for (int q = 0; q < 4; q++) {
            if (vv[q] != 0.f) {
                int p = atomicAdd(&cnt, 1);
                if (p < MAXNB) {
                    g_col[i * MAXNB + p] = c4 * 4 + q;
                    g_adjv[i * MAXNB + p] = vv[q];
                }
            }
        }
    }
    __syncthreads();
    if (threadIdx.x == 0) g_cnt[i] = cnt < MAXNB ? cnt : MAXNB;
}

// ---------------- fp32 -> bf16 hi/lo split ----------------
__global__ void k_split(const float* __restrict__ X,
                        __nv_bfloat16* __restrict__ hi,
                        __nv_bfloat16* __restrict__ lo, int n4) {
    int idx = blockIdx.x * 256 + threadIdx.x;
    if (idx >= n4) return;
    float4 v = __ldcs(reinterpret_cast<const float4*>(X) + idx);
    float xs[4] = {v.x, v.y, v.z, v.w};
    __nv_bfloat16 h[4], l[4];
#pragma unroll
    for (int q = 0; q < 4; q++) {
        h[q] = __float2bfloat16(xs[q]);
        l[q] = __float2bfloat16(xs[q] - __bfloat162float(h[q]));
    }
    __nv_bfloat162* hp = reinterpret_cast<__nv_bfloat162*>(hi) + idx * 2;
    __nv_bfloat162* lp = reinterpret_cast<__nv_bfloat162*>(lo) + idx * 2;
    hp[0] = __nv_bfloat162(h[0], h[1]); hp[1] = __nv_bfloat162(h[2], h[3]);
    lp[0] = __nv_bfloat162(l[0], l[1]); lp[1] = __nv_bfloat162(l[2], l[3]);
}

// ---------------- mma.sync bf16 GEMM with ldmatrix ----------------
// 3xBF16: C = Ah*Bh + Ah*Bl + Al*Bh. CTA tile 128x128; 8 warps of 64x32.
// grid.y tiles the (possibly merged) weight rows. Epilogue routes column tiles:
//   blockIdx.y <  elu_split : C = Ca + elu + biasa   (cols bnw)
//   blockIdx.y >= elu_split : C = Cb, plain, biasb   (cols bnw - 128*elu_split)
#define G_ROWB   80
#define G_TILE   (128 * G_ROWB)   // 10240
#define G_STAGE  (4 * G_TILE)     // 40960
#define G_SMEM   (2 * G_STAGE)    // 81920

__device__ __forceinline__ void g_issue_chunk(
    uint32_t sst,
    const __nv_bfloat16* __restrict__ Ah, const __nv_bfloat16* __restrict__ Al,
    const __nv_bfloat16* __restrict__ Bh, const __nv_bfloat16* __restrict__ Bl,
    int bm, int bn, int K, int k0, int tid)
{
#pragma unroll
    for (int t = 0; t < 2; t++) {
        int idx = tid + t * 256;
        int row = idx >> 2, q = idx & 3;
        uint32_t so = row * G_ROWB + q * 16;
        cp16(sst + so,              Ah + (size_t)(bm + row) * K + k0 + q * 8);
        cp16(sst + G_TILE + so,     Al + (size_t)(bm + row) * K + k0 + q * 8);
        cp16(sst + 2 * G_TILE + so, Bh + (size_t)(bn + row) * K + k0 + q * 8);
        cp16(sst + 3 * G_TILE + so, Bl + (size_t)(bn + row) * K + k0 + q * 8);
    }
    CP_COMMIT();
}

__global__ __launch_bounds__(256, 2)
void k_mma_gemm(const __nv_bfloat16* __restrict__ Ah, const __nv_bfloat16* __restrict__ Al,
                const __nv_bfloat16* __restrict__ Bh, const __nv_bfloat16* __restrict__ Bl,
                const float* __restrict__ biasa, const float* __restrict__ biasb,
                float* __restrict__ Ca, float* __restrict__ Cb,
                int K, int elu_split)
{
    extern __shared__ char smem[];
    uint32_t sb = smem_to_u32(smem);
    int tid = threadIdx.x;
    int wid = tid >> 5, lane = tid & 31;
    int wm = wid >> 2, wn = wid & 3;        // warp tile: rows wm*64, cols wn*32
    int gid = lane >> 2, tk = (lane & 3) * 2;
    int bm = blockIdx.x * 128, bnw = blockIdx.y * 128;

    // ldmatrix per-lane offsets
    uint32_t a_lane = (uint32_t)(((lane & 7) + ((lane >> 3) & 1) * 8) * G_ROWB
                                 + (lane >> 4) * 16);
    uint32_t b_lane = (uint32_t)(((lane & 7) + (lane >> 4) * 8) * G_ROWB
                                 + ((lane >> 3) & 1) * 16);

    float d[4][4][4];
#pragma unroll
    for (int ma = 0; ma < 4; ma++)
#pragma unroll
        for (int na = 0; na < 4; na++)
#pragma unroll
            for (int q = 0; q < 4; q++) d[ma][na][q] = 0.f;

    int NC = K / 32;
    g_issue_chunk(sb, Ah, Al, Bh, Bl, bm, bnw, K, 0, tid);

    for (int c = 0; c < NC; c++) {
        bool more = (c + 1 < NC);
        if (more) {
            g_issue_chunk(sb + ((c + 1) & 1) * G_STAGE, Ah, Al, Bh, Bl,
                          bm, bnw, K, (c + 1) * 32, tid);
            CP_WAIT1();
        } else {
            CP_WAIT0();
        }
        __syncthreads();

        uint32_t st = sb + (c & 1) * G_STAGE;
        uint32_t sAh = st, sAl = st + G_TILE;
        uint32_t sBh = st + 2 * G_TILE, sBl = st + 3 * G_TILE;

#pragma unroll
        for (int kk2 = 0; kk2 < 2; kk2++) {
            uint32_t ko = (uint32_t)(kk2 * 32);   // 16 bf16 = 32 bytes
            // B fragments: two x4 loads cover na pairs (0,1) and (2,3)
            uint32_t bh[4][2], bl[4][2];
#pragma unroll
            for (int p = 0; p < 2; p++) {
                uint32_t boff = (uint32_t)((wn * 32 + p * 16) * G_ROWB) + ko + b_lane;
                uint32_t rh[4], rl[4];
                ldsm_x4(rh, sBh + boff);
                ldsm_x4(rl, sBl + boff);
                bh[p * 2][0] = rh[0]; bh[p * 2][1] = rh[1];
                bh[p * 2 + 1][0] = rh[2]; bh[p * 2 + 1][1] = rh[3];
                bl[p * 2][0] = rl[0]; bl[p * 2][1] = rl[1];
                bl[p * 2 + 1][0] = rl[2]; bl[p * 2 + 1][1] = rl[3];
            }
#pragma unroll
            for (int ma = 0; ma < 4; ma++) {
                uint32_t aoff = (uint32_t)((wm * 64 + ma * 16) * G_ROWB) + ko + a_lane;
                uint32_t ah[4], al[4];
                ldsm_x4(ah, sAh + aoff);
                ldsm_x4(al, sAl + aoff);
#pragma unroll
                for (int na = 0; na < 4; na++) {
                    mma16816(d[ma][na], ah, bh[na]);
                    mma16816(d[ma][na], ah, bl[na]);
                    mma16816(d[ma][na], al, bh[na]);
                }
            }
        }
        __syncthreads();
    }

    // epilogue
    bool first = (blockIdx.y < (unsigned)elu_split);
    float* C = first ? Ca : Cb;
    const float* bias = first ? biasa : biasb;
    int coloff = first ? bnw : bnw - elu_split * 128;
#pragma unroll
    for (int ma = 0; ma < 4; ma++) {
        int r0 = bm + wm * 64 + ma * 16 + gid;
#pragma unroll
        for (int na = 0; na < 4; na++) {
            int col = coloff + wn * 32 + na * 8 + tk;
            float b0 = bias[col], b1 = bias[col + 1];
            float v0 = d[ma][na][0] + b0, v1 = d[ma][na][1] + b1;
            float v2 = d[ma][na][2] + b0, v3 = d[ma][na][3] + b1;
            if (first) { v0 = eluf(v0); v1 = eluf(v1); v2 = eluf(v2); v3 = eluf(v3); }
            *reinterpret_cast<float2*>(C + (size_t)r0 * 256 + col)       = make_float2(v0, v1);
            *reinterpret_cast<float2*>(C + (size_t)(r0 + 8) * 256 + col) = make_float2(v2, v3);
        }
    }
}

// ---------------- small GEMM for layer 2 (Nc=16) ----------------
__global__ __launch_bounds__(256) void k_gemm_small(
    const float* __restrict__ A, const float* __restrict__ W,
    const float* __restrict__ bias, float* __restrict__ C,
    int M, int Nc, int K)
{
    __shared__ float Ws[CLS][HID];
    int tid = threadIdx.x;
    for (int idx = tid; idx < Nc * K; idx += 256)
        Ws[idx / K][idx % K] = W[idx];
    __syncthreads();
    int row = blockIdx.x * 8 + (tid >> 5);
    int lane = tid & 31;
    const float4* ap = reinterpret_cast<const float4*>(A + (size_t)row * K);
    float4 a0 = ap[lane];
    float4 a1 = ap[lane + 32];
    float accv[CLS];
#pragma unroll
    for (int c = 0; c < CLS; c++) {
        float4 w0 = *reinterpret_cast<const float4*>(&Ws[c][lane * 4]);
        float4 w1 = *reinterpret_cast<const float4*>(&Ws[c][lane * 4 + 128]);
        float s = a0.x * w0.x + a0.y * w0.y + a0.z * w0.z + a0.w * w0.w
                + a1.x * w1.x + a1.y * w1.y + a1.z * w1.z + a1.w * w1.w;
#pragma unroll
        for (int o = 16; o; o >>= 1) s += __shfl_xor_sync(0xffffffffu, s, o);
        accv[c] = s + bias[c];
    }
    if (lane < CLS) C[(size_t)row * CLS + lane] = accv[lane];
}

// ---------------- row L2 norms (float4) ----------------
__global__ void k_rownorm(const float* __restrict__ Wh, int D) {
    int row = blockIdx.x * 8 + (threadIdx.x >> 5);
    int lane = threadIdx.x & 31;
    float s = 0.f;
    for (int d = lane * 4; d < D; d += 128) {
        float4 v = *reinterpret_cast<const float4*>(Wh + (size_t)row * D + d);
        s += v.x * v.x + v.y * v.y + v.z * v.z + v.w * v.w;
    }
#pragma unroll
    for (int o = 16; o; o >>= 1) s += __shfl_xor_sync(0xffffffffu, s, o);
    if (lane == 0) g_norm[row] = sqrtf(s);
}

// ---------------- sparse attention + aggregation (+fused residual / split) ----------------
template<int D, bool RES, bool SPLIT>
__global__ __launch_bounds__(256) void k_sparse(
    const float* __restrict__ Wh, float* __restrict__ out,
    const float* __restrict__ dc, const float* __restrict__ co,
    const float* __restrict__ sp, float coef,
    __nv_bfloat16* __restrict__ phi, __nv_bfloat16* __restrict__ plo)
{
    int i = blockIdx.x;
    int tid = threadIdx.x, w = tid >> 5, lane = tid & 31;
    __shared__ float whi[D];
    __shared__ float red[8][D];
    for (int d = tid; d < D; d += 256) whi[d] = Wh[(size_t)i * D + d];
    __syncthreads();
    float ni = g_norm[i];
    float diag = g_diag[i];
    float dc0 = dc[0], dc1 = dc[1];
    int nn = g_cnt[i];

    float pp, nv;

    if constexpr (D == 256) {
        float4 wi0 = *reinterpret_cast<const float4*>(&whi[lane * 4]);
        float4 wi1 = *reinterpret_cast<const float4*>(&whi[lane * 4 + 128]);
        float4 ap0 = make_float4(0, 0, 0, 0), ap1 = ap0, an0 = ap0, an1 = ap0;
        for (int t = w; t < nn; t += 16) {
            int t1 = t + 8;
            bool h1 = t1 < nn;
            int o0 = i * MAXNB + t;
            int o1 = i * MAXNB + (h1 ? t1 : t);
            int j0 = g_col[o0]; float a0 = g_adjv[o0];
            int j1 = g_col[o1]; float a1 = g_adjv[o1];
            const float4* wj0 = reinterpret_cast<const float4*>(Wh + (size_t)j0 * D);
            const float4* wj1 = reinterpret_cast<const float4*>(Wh + (size_t)j1 * D);
            float4 u0 = wj0[lane], u1 = wj0[lane + 32];
            float4 q0 = wj1[lane], q1 = wj1[lane + 32];
            float p0 = wi0.x * u0.x + wi0.y * u0.y + wi0.z * u0.z + wi0.w * u0.w
                     + wi1.x * u1.x + wi1.y * u1.y + wi1.z * u1.z + wi1.w * u1.w;
            float p1 = wi0.x * q0.x + wi0.y * q0.y + wi0.z * q0.z + wi0.w * q0.w
                     + wi1.x * q1.x + wi1.y * q1.y + wi1.z * q1.z + wi1.w * q1.w;
#pragma unroll
            for (int o = 16; o; o >>= 1) {
                p0 += __shfl_xor_sync(0xffffffffu, p0, o);
                p1 += __shfl_xor_sync(0xffffffffu, p1, o);
            }
            float e0 = p0 / fmaxf(ni * g_norm[j0], 1e-9f);
            float e1 = p1 / fmaxf(ni * g_norm[j1], 1e-9f);
            float sc0 = softplusf(dc0 * (diag / a0 - 1.f) + dc1);
            float sc1 = softplusf(dc0 * (diag / a1 - 1.f) + dc1);
            float att0 = (j0 == i) ? 0.f : e0 * a0 * sc0;
            float att1 = (j1 == i || !h1) ? 0.f : e1 * a1 * sc1;
            float wp0 = fmaxf(att0, 0.f), wn0 = fminf(att0, 0.f);
            float wp1 = fmaxf(att1, 0.f), wn1 = fminf(att1, 0.f);
            ap0.x += wp0 * u0.x + wp1 * q0.x; ap0.y += wp0 * u0.y + wp1 * q0.y;
            ap0.z += wp0 * u0.z + wp1 * q0.z; ap0.w += wp0 * u0.w + wp1 * q0.w;
            ap1.x += wp0 * u1.x + wp1 * q1.x; ap1.y += wp0 * u1.y + wp1 * q1.y;
            ap1.z += wp0 * u1.z + wp1 * q1.z; ap1.w += wp0 * u1.w + wp1 * q1.w;
            an0.x += wn0 * u0.x + wn1 * q0.x; an0.y += wn0 * u0.y + wn1 * q0.y;
            an0.z += wn0 * u0.z + wn1 * q0.z; an0.w += wn0 * u0.w + wn1 * q0.w;
            an1.x += wn0 * u1.x + wn1 * q1.x; an1.y += wn0 * u1.y + wn1 * q1.y;
            an1.z += wn0 * u1.z + wn1 * q1.z; an1.w += wn0 * u1.w + wn1 * q1.w;
        }
        *reinterpret_cast<float4*>(&red[w][lane * 4]) = ap0;
        *reinterpret_cast<float4*>(&red[w][lane * 4 + 128]) = ap1;
        __syncthreads();
        pp = 0.f;
#pragma unroll
        for (int ww = 0; ww < 8; ww++) pp += red[ww][tid];
        __syncthreads();
        *reinterpret_cast<float4*>(&red[w][lane * 4]) = an0;
        *reinterpret_cast<float4*>(&red[w][lane * 4 + 128]) = an1;
        __syncthreads();
        nv = 0.f;
#pragma unroll
        for (int ww = 0; ww < 8; ww++) nv += red[ww][tid];
    } else {
        float wi = (lane < D) ? whi[lane] : 0.f;
        float ap = 0.f, an = 0.f;
        for (int t = w; t < nn; t += 8) {
            int j = g_col[i * MAXNB + t];
            float a = g_adjv[i * MAXNB + t];
            if (j == i) continue;
            float v = (lane < D) ? Wh[(size_t)j * D + lane] : 0.f;
            float p = wi * v;
#pragma unroll
            for (int o = 16; o; o >>= 1) p += __shfl_xor_sync(0xffffffffu, p, o);
            float denom = fmaxf(ni * g_norm[j], 1e-9f);
            float e = p / denom;
            float deg = diag / a - 1.f;
            float sc = softplusf(dc0 * deg + dc1);
            float att = e * a * sc;
            ap += fmaxf(att, 0.f) * v;
            an += fminf(att, 0.f) * v;
        }
        if (lane < D) red[w][lane] = ap;
        __syncthreads();
        pp = 0.f;
        if (tid < D) {
#pragma unroll
            for (int ww = 0; ww < 8; ww++) pp += red[ww][tid];
        }
        __syncthreads();
        if (lane < D) red[w][lane] = an;
        __syncthreads();
        nv = 0.f;
        if (tid < D) {
#pragma unroll
            for (int ww = 0; ww < 8; ww++) nv += red[ww][tid];
        }
    }

    if (tid < D) {
        float m = fmaxf(co[0], fmaxf(co[1], co[2]));
        float e0 = expf(co[0] - m), e1 = expf(co[1] - m), e2 = expf(co[2] - m);
        float sden = e0 + e1 + e2;
        float c0 = e0 / sden, c1 = e1 / sden, c2 = e2 / sden;
        float s = softplusf(sp[0]);
        float val = s * (c0 * pp + c1 * nv + c2 * whi[tid]);
        if (RES) {
            float newv = out[(size_t)i * D + tid] + coef * eluf(val);
            out[(size_t)i * D + tid] = newv;
            if (SPLIT) {
                __nv_bfloat16 h = __float2bfloat16(newv);
                phi[(size_t)i * D + tid] = h;
                plo[(size_t)i * D + tid] =
                    __float2bfloat16(newv - __bfloat162float(h));
            }
        } else {
            out[(size_t)i * D + tid] = val;
        }
    }
}

// ---------------- head: log_softmax + softmax + top2 ----------------
__global__ void k_head(const float* __restrict__ C, float* __restrict__ logp,
                       float* __restrict__ pred) {
    int g = threadIdx.x >> 4;
    int l = threadIdx.x & 15;
    int row = blockIdx.x * 16 + g;
    float x = C[row * CLS + l];
    float m = x;
#pragma unroll
    for (int o = 8; o; o >>= 1) m = fmaxf(m, __shfl_xor_sync(0xffffffffu, m, o, 16));
    float ex = expf(x - m);
    float se = ex;
#pragma unroll
    for (int o = 8; o; o >>= 1) se += __shfl_xor_sync(0xffffffffu, se, o, 16);
    float lse = logf(se);
    logp[row * CLS + l] = x - m - lse;
    float pr = ex / se;
    pred[row * CLS + l] = pr;
    int laneid = threadIdx.x & 31;
    int segbase = laneid & 16;
    float m1 = -1.f, m2 = -1.f;
#pragma unroll
    for (int k = 0; k < 16; k++) {
        float v = __shfl_sync(0xffffffffu, pr, segbase + k);
        if (v > m1) { m2 = m1; m1 = v; }
        else if (v > m2) m2 = v;
    }
    if (l == 0) g_t2[row] = m1 + m2;
}

// ---------------- deterministic calib reduction ----------------
__global__ void k_calib(float* __restrict__ out_calib) {
    __shared__ float sh[256];
    float s = 0.f;
    for (int i = threadIdx.x; i < NV; i += 256) s += g_t2[i];
    sh[threadIdx.x] = s;
    __syncthreads();
    for (int o = 128; o; o >>= 1) {
        if (threadIdx.x < o) sh[threadIdx.x] += sh[threadIdx.x + o];
        __syncthreads();
    }
    if (threadIdx.x == 0) out_calib[0] = sh[0] / (float)NV;
}

// ---------------- launcher ----------------
extern "C" void kernel_launch(void* const* d_in, const int* in_sizes, int n_in,
                              void* d_out, int out_size) {
    const float* x    = (const float*)d_in[0];
    const float* adj  = (const float*)d_in[1];
    const float* fcnW = (const float*)d_in[2];
    const float* fcnb = (const float*)d_in[3];
    const float* W0   = (const float*)d_in[4];
    const float* b0   = (const float*)d_in[5];
    const float* dc0  = (const float*)d_in[6];
    const float* c0   = (const float*)d_in[7];
    const float* s0   = (const float*)d_in[8];
    const float* W1   = (const float*)d_in[9];
    const float* b1   = (const float*)d_in[10];
    const float* dc1  = (const float*)d_in[11];
    const float* c1   = (const float*)d_in[12];
    const float* s1   = (const float*)d_in[13];
    const float* W2   = (const float*)d_in[14];
    const float* b2   = (const float*)d_in[15];
    const float* dc2  = (const float*)d_in[16];
    const float* c2   = (const float*)d_in[17];
    const float* s2   = (const float*)d_in[18];

    float* out       = (float*)d_out;
    float* out_logp  = out;
    float* out_calib = out + NV * CLS;
    float* out_pred  = out + NV * CLS + 1;

    float *pP, *pA, *pC16, *pO16;
    cudaGetSymbolAddress((void**)&pP,   g_P);
    cudaGetSymbolAddress((void**)&pA,   g_A);
    cudaGetSymbolAddress((void**)&pC16, g_C16);
    cudaGetSymbolAddress((void**)&pO16, g_O16);
    __nv_bfloat16 *pxh, *pxl, *pph, *ppl, *pwh, *pwl;
    cudaGetSymbolAddress((void**)&pxh, g_xhi);
    cudaGetSymbolAddress((void**)&pxl, g_xlo);
    cudaGetSymbolAddress((void**)&pph, g_phi);
    cudaGetSymbolAddress((void**)&ppl, g_plo);
    cudaGetSymbolAddress((void**)&pwh, g_whi);
    cudaGetSymbolAddress((void**)&pwl, g_wlo);

    cudaFuncSetAttribute(k_mma_gemm, cudaFuncAttributeMaxDynamicSharedMemorySize, G_SMEM);

    // CSR from adjacency (also extracts diag)
    k_build_csr<<<NV, 256>>>(adj);

    // split x once
    k_split<<<(NV * FEAT / 4 + 255) / 256, 256>>>(x, pxh, pxl, NV * FEAT / 4);

    // merged weights: rows 0-255 = fcnW, rows 256-511 = W0
    k_split<<<(HID * FEAT / 4 + 255) / 256, 256>>>(fcnW, pwh, pwl, HID * FEAT / 4);
    k_split<<<(HID * FEAT / 4 + 255) / 256, 256>>>(W0, pwh + HID * FEAT,
                                                   pwl + HID * FEAT, HID * FEAT / 4);
    // merged GEMM: prev = elu(x@fcnW^T+fcnb)  AND  Wh0 = x@W0^T+b0
    k_mma_gemm<<<dim3(NV / 128, 4), 256, G_SMEM>>>(pxh, pxl, pwh, pwl,
                                                   fcnb, b0, pP, pA, FEAT, 2);
    k_rownorm<<<NV / 8, 256>>>(pA, HID);
    // layer 0 sparse, fused residual into P + write bf16 split of new P
    k_sparse<HID, true, true><<<NV, 256>>>(pA, pP, dc0, c0, s0, 1.0f, pph, ppl);

    // ---- layer 1 (input prev) ----
    k_split<<<(HID * HID / 4 + 255) / 256, 256>>>(W1, pwh, pwl, HID * HID / 4);
    k_mma_gemm<<<dim3(NV / 128, 2), 256, G_SMEM>>>(pph, ppl, pwh, pwl,
                                                   b1, b1, pA, pA, HID, 0);
    k_rownorm<<<NV / 8, 256>>>(pA, HID);
    float decay = (float)log(0.9 / 27.0 + 1.0);
    k_sparse<HID, true, false><<<NV, 256>>>(pA, pP, dc1, c1, s1, decay, pph, ppl);

    // ---- layer 2 (input prev, D=16) ----
    k_gemm_small<<<NV / 8, 256>>>(pP, W2, b2, pC16, NV, CLS, HID);
    k_rownorm<<<NV / 8, 256>>>(pC16, CLS);
    k_sparse<CLS, false, false><<<NV, 256>>>(pC16, pO16, dc2, c2, s2, 0.0f, pph, ppl);

    // ---- head ----
    k_head<<<NV / 16, 256>>>(pO16, out_logp, out_pred);
    k_calib<<<1, 256>>>(out_calib);
}